// round 4
// baseline (speedup 1.0000x reference)
#include <cuda_runtime.h>
#include <cuda_bf16.h>
#include <math.h>

// Problem constants
#define Bn   128
#define Cn   256
#define Nn   4096
#define CQn  64
#define CHUNK 256            // n-points per block in kernel B
#define NCHUNK (Nn / CHUNK)  // 16

// ---------------- scratch (no allocations allowed) ----------------
__device__ float g_tk[Bn * CQn];        // tanh(k)  (B, 64)
__device__ float g_energy[Bn * Nn];     // (B, N)
__device__ float g_s[Bn * Cn];          // weighted sums (B, C)
__device__ float g_t[Bn * Cn];          // pre-BN t (B, C)

// ---------------- f32x2 helpers ----------------
__device__ __forceinline__ void fma2(unsigned long long& acc,
                                     unsigned long long a,
                                     unsigned long long b) {
    asm("fma.rn.f32x2 %0, %1, %2, %0;" : "+l"(acc) : "l"(a), "l"(b));
}
__device__ __forceinline__ void unpack2(unsigned long long v, float& lo, float& hi) {
    asm("mov.b64 {%0, %1}, %2;" : "=f"(lo), "=f"(hi) : "l"(v));
}

// ---------------- Kernel A: tk[b,o] = tanh(wk . x_key[b] + bk) ----------------
__global__ void kA(const float* __restrict__ x_key, const float* __restrict__ wk,
                   const float* __restrict__ bk) {
    __shared__ float xk[Cn];
    int b = blockIdx.x;
    for (int i = threadIdx.x; i < Cn; i += 64) xk[i] = x_key[b * Cn + i];
    __syncthreads();
    int o = threadIdx.x;
    float acc = bk[o];
    const float* wr = wk + o * Cn;
    #pragma unroll 8
    for (int c = 0; c < Cn; c++) acc = fmaf(wr[c], xk[c], acc);
    g_tk[b * CQn + o] = tanhf(acc);
}

// ---------------- Kernel B: energy[b,n] = sum_o tanh(wq.x + bq) * tk ----------------
// Register-tiled GEMM: per block 64(o) x 256(n) x 256(k), f32x2 packed FMAs.
// Thread (ty,tx): ty = warp (8), tx = lane (32). Each thread: 8 o x 4 n-pairs.
__global__ __launch_bounds__(256, 2) void kB(const float* __restrict__ x,
                                             const float* __restrict__ wq,
                                             const float* __restrict__ bq) {
    extern __shared__ float sm[];
    float*  x_s   = sm;                       // [64][256]  (k, n)   65536 B
    float2* wq_s2 = (float2*)(sm + 64 * 256); // [64][64]   dup pairs 32768 B
    float*  e_red = sm + 64 * 256 + 64 * 64 * 2; // [8][256] 8192 B
    float*  tk_s  = e_red + 8 * 256;          // [64]
    float*  bq_s  = tk_s + 64;                // [64]

    const int b  = blockIdx.x >> 4;
    const int n0 = (blockIdx.x & 15) * CHUNK;
    const int tid = threadIdx.x;
    const int tx = tid & 31, ty = tid >> 5;

    if (tid < 64) {
        tk_s[tid] = g_tk[b * CQn + tid];
        bq_s[tid] = bq[tid];
    }

    unsigned long long acc[8][4];
    #pragma unroll
    for (int i = 0; i < 8; i++)
        #pragma unroll
        for (int j = 0; j < 4; j++) acc[i][j] = 0ull;

    for (int ksub = 0; ksub < 4; ksub++) {
        // load x tile [64 c][256 n] via float4, coalesced
        {
            float4* xs4 = (float4*)x_s;
            for (int idx = tid; idx < 64 * 64; idx += 256) {
                int cc = idx >> 6, p = idx & 63;
                const float4* row =
                    (const float4*)(x + ((size_t)(b * Cn + ksub * 64 + cc)) * Nn + n0);
                xs4[cc * 64 + p] = row[p];
            }
        }
        // load wq sub-tile, duplicated pairs: wq_s2[k][o] = {w,w}
        for (int idx = tid; idx < 64 * 64; idx += 256) {
            int o = idx & 63, k = idx >> 6;
            float w = wq[o * Cn + ksub * 64 + k];
            wq_s2[(k << 6) + o] = make_float2(w, w);
        }
        __syncthreads();

        #pragma unroll 2
        for (int k = 0; k < 64; k++) {
            const unsigned long long* arow =
                (const unsigned long long*)(wq_s2 + (k << 6) + (ty << 3));
            const float* brow = x_s + (k << 8);
            unsigned long long b0 = *(const unsigned long long*)(brow + 2 * tx);
            unsigned long long b1 = *(const unsigned long long*)(brow + 2 * tx + 64);
            unsigned long long b2 = *(const unsigned long long*)(brow + 2 * tx + 128);
            unsigned long long b3 = *(const unsigned long long*)(brow + 2 * tx + 192);
            #pragma unroll
            for (int i = 0; i < 8; i++) {
                unsigned long long a = arow[i];
                fma2(acc[i][0], a, b0);
                fma2(acc[i][1], a, b1);
                fma2(acc[i][2], a, b2);
                fma2(acc[i][3], a, b3);
            }
        }
        __syncthreads();
    }

    // epilogue: per-thread partial energy over its 8 o's, for its 8 n's
    float ep[8] = {0, 0, 0, 0, 0, 0, 0, 0};
    #pragma unroll
    for (int i = 0; i < 8; i++) {
        int o = (ty << 3) + i;
        float tko = tk_s[o], bqo = bq_s[o];
        #pragma unroll
        for (int j = 0; j < 4; j++) {
            float q0, q1;
            unpack2(acc[i][j], q0, q1);
            ep[2 * j]     += tanhf(q0 + bqo) * tko;
            ep[2 * j + 1] += tanhf(q1 + bqo) * tko;
        }
    }
    #pragma unroll
    for (int j = 0; j < 4; j++) {
        int p = tx + 32 * j;
        e_red[ty * 256 + 2 * p]     = ep[2 * j];
        e_red[ty * 256 + 2 * p + 1] = ep[2 * j + 1];
    }
    __syncthreads();
    float e = 0.f;
    #pragma unroll
    for (int r = 0; r < 8; r++) e += e_red[r * 256 + tid];
    g_energy[(size_t)b * Nn + n0 + tid] = e;
}

// ---------------- Kernel C: softmax over N per batch -> att (into d_out) ------
__global__ void kC(float* __restrict__ att_out) {
    __shared__ float red[256];
    int b = blockIdx.x, tid = threadIdx.x;
    const float* e = g_energy + (size_t)b * Nn;
    float m = -1e30f;
    for (int i = tid; i < Nn; i += 256) m = fmaxf(m, e[i]);
    red[tid] = m; __syncthreads();
    for (int s = 128; s > 0; s >>= 1) {
        if (tid < s) red[tid] = fmaxf(red[tid], red[tid + s]);
        __syncthreads();
    }
    m = red[0]; __syncthreads();
    float z = 0.f;
    for (int i = tid; i < Nn; i += 256) z += expf(e[i] - m);
    red[tid] = z; __syncthreads();
    for (int s = 128; s > 0; s >>= 1) {
        if (tid < s) red[tid] += red[tid + s];
        __syncthreads();
    }
    float inv = 1.f / red[0];
    float* out = att_out + (size_t)b * Nn;
    for (int i = tid; i < Nn; i += 256) out[i] = expf(e[i] - m) * inv;
}

// ---------------- Kernel D: s[b,c] = dot(x[b,c,:], att[b,:]) ----------------
__global__ void kD(const float* __restrict__ x, const float* __restrict__ att) {
    int row = blockIdx.x * 8 + (threadIdx.x >> 5);   // row = b*C + c
    int lane = threadIdx.x & 31;
    int b = row >> 8;
    const float4* xr = (const float4*)(x + (size_t)row * Nn);
    const float4* ar = (const float4*)(att + (size_t)b * Nn);
    float acc = 0.f;
    #pragma unroll 4
    for (int i = lane; i < Nn / 4; i += 32) {
        float4 xv = xr[i], av = ar[i];
        acc += xv.x * av.x + xv.y * av.y + xv.z * av.z + xv.w * av.w;
    }
    #pragma unroll
    for (int o = 16; o > 0; o >>= 1) acc += __shfl_down_sync(0xffffffffu, acc, o);
    if (lane == 0) g_s[row] = acc;
}

// ---------------- Kernel E1: r = wv.s + bv ; t = wt.(x_key - r) + bt ----------
__global__ void kE1(const float* __restrict__ x_key,
                    const float* __restrict__ wv, const float* __restrict__ bv,
                    const float* __restrict__ wt, const float* __restrict__ bt) {
    __shared__ float s_sm[Cn], u_sm[Cn];
    int b = blockIdx.x, c = threadIdx.x;
    s_sm[c] = g_s[b * Cn + c];
    float xk = x_key[b * Cn + c];
    __syncthreads();
    float r = bv[c];
    const float* wr = wv + c * Cn;
    #pragma unroll 8
    for (int c2 = 0; c2 < Cn; c2++) r = fmaf(wr[c2], s_sm[c2], r);
    u_sm[c] = xk - r;
    __syncthreads();
    float tv = bt[c];
    const float* wr2 = wt + c * Cn;
    #pragma unroll 8
    for (int c2 = 0; c2 < Cn; c2++) tv = fmaf(wr2[c2], u_sm[c2], tv);
    g_t[b * Cn + c] = tv;
}

// ---------------- Kernel E2: BN (batch stats) + ReLU + residual --------------
__global__ void kE2(const float* __restrict__ x_key, const float* __restrict__ gamma,
                    const float* __restrict__ beta, float* __restrict__ out) {
    __shared__ float rs[128], rs2[128];
    int c = blockIdx.x, b = threadIdx.x;
    float tv = g_t[b * Cn + c];
    rs[b] = tv; rs2[b] = tv * tv;
    __syncthreads();
    for (int s = 64; s > 0; s >>= 1) {
        if (b < s) { rs[b] += rs[b + s]; rs2[b] += rs2[b + s]; }
        __syncthreads();
    }
    float mean = rs[0] * (1.f / Bn);
    float var  = rs2[0] * (1.f / Bn) - mean * mean;
    float val = (tv - mean) * rsqrtf(var + 1e-5f) * gamma[c] + beta[c];
    out[b * Cn + c] = x_key[b * Cn + c] + fmaxf(val, 0.f);
}

// ---------------- launch ----------------
extern "C" void kernel_launch(void* const* d_in, const int* in_sizes, int n_in,
                              void* d_out, int out_size) {
    const float* x     = (const float*)d_in[0];
    const float* x_key = (const float*)d_in[1];
    const float* wq    = (const float*)d_in[2];
    const float* bq    = (const float*)d_in[3];
    const float* wk    = (const float*)d_in[4];
    const float* bk    = (const float*)d_in[5];
    const float* wv    = (const float*)d_in[6];
    const float* bv    = (const float*)d_in[7];
    const float* wt    = (const float*)d_in[8];
    const float* bt    = (const float*)d_in[9];
    const float* gamma = (const float*)d_in[10];
    const float* beta  = (const float*)d_in[11];

    float* out_final = (float*)d_out;               // (B, C)
    float* out_att   = (float*)d_out + Bn * Cn;     // (B, N)

    const int smemB = (64 * 256 + 64 * 64 * 2 + 8 * 256 + 128) * sizeof(float);
    cudaFuncSetAttribute(kB, cudaFuncAttributeMaxDynamicSharedMemorySize, smemB);

    kA<<<Bn, 64>>>(x_key, wk, bk);
    kB<<<Bn * NCHUNK, 256, smemB>>>(x, wq, bq);
    kC<<<Bn, 256>>>(out_att);
    kD<<<(Bn * Cn) / 8, 256>>>(x, out_att);
    kE1<<<Bn, Cn>>>(x_key, wv, bv, wt, bt);
    kE2<<<Cn, Bn>>>(x_key, gamma, beta, out_final);
}

// round 8
// speedup vs baseline: 1.9157x; 1.9157x over previous
#include <cuda_runtime.h>
#include <cuda_bf16.h>
#include <cstdint>
#include <math.h>

// Problem constants
#define Bn   128
#define Cn   256
#define Nn   4096
#define CQn  64
#define NBB  128             // n-points per block in kBm
#define NCH  (Nn / NBB)      // 32

// ---------------- scratch ----------------
__device__ float g_tk[Bn * CQn];        // tanh(k)  (B, 64)
__device__ float g_energy[Bn * Nn];     // (B, N)
__device__ float g_s[Bn * Cn];          // weighted sums (B, C)
__device__ float g_t[Bn * Cn];          // pre-BN t (B, C)

// ---------------- helpers ----------------
__device__ __forceinline__ uint32_t smem_u32(const void* p) {
    uint32_t a;
    asm("{ .reg .u64 t; cvta.to.shared.u64 t, %1; cvt.u32.u64 %0, t; }" : "=r"(a) : "l"(p));
    return a;
}
__device__ __forceinline__ void ldsm_x4(uint32_t* r, uint32_t a) {
    asm volatile("ldmatrix.sync.aligned.m8n8.x4.shared.b16 {%0,%1,%2,%3}, [%4];"
                 : "=r"(r[0]), "=r"(r[1]), "=r"(r[2]), "=r"(r[3]) : "r"(a));
}
__device__ __forceinline__ void ldsm_x2t(uint32_t* r, uint32_t a) {
    asm volatile("ldmatrix.sync.aligned.m8n8.x2.trans.shared.b16 {%0,%1}, [%2];"
                 : "=r"(r[0]), "=r"(r[1]) : "r"(a));
}
__device__ __forceinline__ void mma16816(float* c, const uint32_t* a, const uint32_t* b) {
    asm volatile(
        "mma.sync.aligned.m16n8k16.row.col.f32.bf16.bf16.f32 "
        "{%0,%1,%2,%3}, {%4,%5,%6,%7}, {%8,%9}, {%0,%1,%2,%3};"
        : "+f"(c[0]), "+f"(c[1]), "+f"(c[2]), "+f"(c[3])
        : "r"(a[0]), "r"(a[1]), "r"(a[2]), "r"(a[3]), "r"(b[0]), "r"(b[1]));
}
__device__ __forceinline__ void pack4_split(float4 v, uint2& hi, uint2& lo) {
    __nv_bfloat16 h0 = __float2bfloat16(v.x), h1 = __float2bfloat16(v.y);
    __nv_bfloat16 h2 = __float2bfloat16(v.z), h3 = __float2bfloat16(v.w);
    float r0 = v.x - __bfloat162float(h0), r1 = v.y - __bfloat162float(h1);
    float r2 = v.z - __bfloat162float(h2), r3 = v.w - __bfloat162float(h3);
    union { __nv_bfloat16 h[4]; uint2 u; } a, b;
    a.h[0] = h0; a.h[1] = h1; a.h[2] = h2; a.h[3] = h3;
    b.h[0] = __float2bfloat16(r0); b.h[1] = __float2bfloat16(r1);
    b.h[2] = __float2bfloat16(r2); b.h[3] = __float2bfloat16(r3);
    hi = a.u; lo = b.u;
}

// smem layout (bytes): wq rows padded to 72 bf16, x rows to 136 bf16
#define WPITCH 72
#define XPITCH 136
#define OFF_WHI 0                      // 64*72*2  = 9216
#define OFF_WLO 9216                   // 9216
#define OFF_XHI 18432                  // 64*136*2 = 17408
#define OFF_XLO 35840                  // 17408
#define OFF_RED 53248                  // 128*2 f32 = 1024
#define SMEM_TOT 54272

// ---------------- Kernel A: tk[b,o] = tanh(wk . x_key[b] + bk) ----------------
__global__ void kA(const float* __restrict__ x_key, const float* __restrict__ wk,
                   const float* __restrict__ bk) {
    __shared__ float xk[Cn];
    int b = blockIdx.x;
    for (int i = threadIdx.x; i < Cn; i += 64) xk[i] = x_key[b * Cn + i];
    __syncthreads();
    int o = threadIdx.x;
    float acc = bk[o];
    const float* wr = wk + o * Cn;
    #pragma unroll 8
    for (int c = 0; c < Cn; c++) acc = fmaf(wr[c], xk[c], acc);
    g_tk[b * CQn + o] = tanhf(acc);
}

// ---- Kernel B (mma.sync): energy[b,n] = sum_o tanh((wq.x)[o,n]+bq[o]) * tk[o] ----
// Block: (b, 128-n chunk). 8 warps = 2 m-rows (32 o each) x 4 n-cols (32 n each).
// Split-bf16: D = Ah*Bh + Ah*Bl + Al*Bh (lo*lo dropped).
__global__ __launch_bounds__(256, 4) void kBm(const float* __restrict__ x,
                                              const float* __restrict__ wq,
                                              const float* __restrict__ bq) {
    extern __shared__ char sm[];
    __nv_bfloat16* whi = (__nv_bfloat16*)(sm + OFF_WHI);
    __nv_bfloat16* wlo = (__nv_bfloat16*)(sm + OFF_WLO);
    __nv_bfloat16* xhi = (__nv_bfloat16*)(sm + OFF_XHI);
    __nv_bfloat16* xlo = (__nv_bfloat16*)(sm + OFF_XLO);
    float* red = (float*)(sm + OFF_RED);

    const int tid = threadIdx.x, wid = tid >> 5, lane = tid & 31;
    const int b  = blockIdx.x >> 5;
    const int n0 = (blockIdx.x & 31) * NBB;
    const int mrow = wid & 1, ncol = wid >> 1;
    const int g = lane >> 2, tig = lane & 3;

    float acc[2][4][4];
    #pragma unroll
    for (int mt = 0; mt < 2; mt++)
        #pragma unroll
        for (int nt = 0; nt < 4; nt++)
            #pragma unroll
            for (int j = 0; j < 4; j++) acc[mt][nt][j] = 0.f;

    // fragment smem addresses (constant across ksub)
    const uint32_t a_base = smem_u32(whi) + (uint32_t)(((mrow * 32 + (lane & 15)) * WPITCH + (lane >> 4) * 8) * 2);
    const uint32_t b_base = smem_u32(xhi) + (uint32_t)(((lane & 15) * XPITCH + ncol * 32) * 2);
    const uint32_t HL_W = (uint32_t)(OFF_WLO - OFF_WHI);   // whi->wlo delta
    const uint32_t HL_X = (uint32_t)(OFF_XLO - OFF_XHI);

    for (int ksub = 0; ksub < 4; ksub++) {
        // load wq tile [64 o][64 k] -> hi/lo  (1024 float4)
        for (int i = tid; i < 1024; i += 256) {
            int o = i >> 4, k4 = (i & 15) * 4;
            float4 v = *(const float4*)(wq + o * Cn + ksub * 64 + k4);
            uint2 h, l; pack4_split(v, h, l);
            *(uint2*)(whi + o * WPITCH + k4) = h;
            *(uint2*)(wlo + o * WPITCH + k4) = l;
        }
        // load x tile [64 k][128 n] -> hi/lo  (2048 float4)
        for (int i = tid; i < 2048; i += 256) {
            int k = i >> 5, n4 = (i & 31) * 4;
            float4 v = *(const float4*)(x + ((size_t)(b * Cn + ksub * 64 + k)) * Nn + n0 + n4);
            uint2 h, l; pack4_split(v, h, l);
            *(uint2*)(xhi + k * XPITCH + n4) = h;
            *(uint2*)(xlo + k * XPITCH + n4) = l;
        }
        __syncthreads();

        #pragma unroll
        for (int kst = 0; kst < 4; kst++) {
            uint32_t ahi[2][4], alo[2][4];
            uint32_t a_addr = a_base + (uint32_t)(kst * 16 * 2);
            ldsm_x4(ahi[0], a_addr);
            ldsm_x4(alo[0], a_addr + HL_W);
            ldsm_x4(ahi[1], a_addr + (uint32_t)(16 * WPITCH * 2));
            ldsm_x4(alo[1], a_addr + (uint32_t)(16 * WPITCH * 2) + HL_W);

            uint32_t b_addr0 = b_base + (uint32_t)(kst * 16 * XPITCH * 2);
            #pragma unroll
            for (int nt = 0; nt < 4; nt++) {
                uint32_t bh[2], bl[2];
                uint32_t baddr = b_addr0 + (uint32_t)(nt * 8 * 2);
                ldsm_x2t(bh, baddr);
                ldsm_x2t(bl, baddr + HL_X);
                #pragma unroll
                for (int mt = 0; mt < 2; mt++) {
                    mma16816(acc[mt][nt], ahi[mt], bh);
                    mma16816(acc[mt][nt], ahi[mt], bl);
                    mma16816(acc[mt][nt], alo[mt], bh);
                }
            }
        }
        __syncthreads();
    }

    // epilogue: tanh(q + bq)*tk, reduce over o (64)
    float p[4][2];
    #pragma unroll
    for (int nt = 0; nt < 4; nt++) { p[nt][0] = 0.f; p[nt][1] = 0.f; }
    #pragma unroll
    for (int mt = 0; mt < 2; mt++) {
        int ob = mrow * 32 + mt * 16 + g;
        float tk0 = g_tk[b * CQn + ob],     bq0 = bq[ob];
        float tk8 = g_tk[b * CQn + ob + 8], bq8 = bq[ob + 8];
        #pragma unroll
        for (int nt = 0; nt < 4; nt++) {
            p[nt][0] += tanhf(acc[mt][nt][0] + bq0) * tk0 + tanhf(acc[mt][nt][2] + bq8) * tk8;
            p[nt][1] += tanhf(acc[mt][nt][1] + bq0) * tk0 + tanhf(acc[mt][nt][3] + bq8) * tk8;
        }
    }
    #pragma unroll
    for (int mask = 4; mask <= 16; mask <<= 1)
        #pragma unroll
        for (int nt = 0; nt < 4; nt++) {
            p[nt][0] += __shfl_xor_sync(0xffffffffu, p[nt][0], mask);
            p[nt][1] += __shfl_xor_sync(0xffffffffu, p[nt][1], mask);
        }
    if (g == 0) {
        #pragma unroll
        for (int nt = 0; nt < 4; nt++) {
            int n = ncol * 32 + nt * 8 + 2 * tig;
            red[n * 2 + mrow]       = p[nt][0];
            red[(n + 1) * 2 + mrow] = p[nt][1];
        }
    }
    __syncthreads();
    if (tid < NBB)
        g_energy[(size_t)b * Nn + n0 + tid] = red[tid * 2] + red[tid * 2 + 1];
}

// ---------------- Kernel C: softmax over N per batch -> att (into d_out) ------
__global__ void kC(float* __restrict__ att_out) {
    __shared__ float red[256];
    int b = blockIdx.x, tid = threadIdx.x;
    const float* e = g_energy + (size_t)b * Nn;
    float m = -1e30f;
    for (int i = tid; i < Nn; i += 256) m = fmaxf(m, e[i]);
    red[tid] = m; __syncthreads();
    for (int s = 128; s > 0; s >>= 1) {
        if (tid < s) red[tid] = fmaxf(red[tid], red[tid + s]);
        __syncthreads();
    }
    m = red[0]; __syncthreads();
    float z = 0.f;
    for (int i = tid; i < Nn; i += 256) z += expf(e[i] - m);
    red[tid] = z; __syncthreads();
    for (int s = 128; s > 0; s >>= 1) {
        if (tid < s) red[tid] += red[tid + s];
        __syncthreads();
    }
    float inv = 1.f / red[0];
    float* out = att_out + (size_t)b * Nn;
    for (int i = tid; i < Nn; i += 256) out[i] = expf(e[i] - m) * inv;
}

// ---------------- Kernel D: s[b,c] = dot(x[b,c,:], att[b,:]) ----------------
__global__ void kD(const float* __restrict__ x, const float* __restrict__ att) {
    int row = blockIdx.x * 8 + (threadIdx.x >> 5);   // row = b*C + c
    int lane = threadIdx.x & 31;
    int b = row >> 8;
    const float4* xr = (const float4*)(x + (size_t)row * Nn);
    const float4* ar = (const float4*)(att + (size_t)b * Nn);
    float acc = 0.f;
    #pragma unroll 4
    for (int i = lane; i < Nn / 4; i += 32) {
        float4 xv = xr[i], av = ar[i];
        acc += xv.x * av.x + xv.y * av.y + xv.z * av.z + xv.w * av.w;
    }
    #pragma unroll
    for (int o = 16; o > 0; o >>= 1) acc += __shfl_down_sync(0xffffffffu, acc, o);
    if (lane == 0) g_s[row] = acc;
}

// ---------------- Kernel E1: r = wv.s + bv ; t = wt.(x_key - r) + bt ----------
__global__ void kE1(const float* __restrict__ x_key,
                    const float* __restrict__ wv, const float* __restrict__ bv,
                    const float* __restrict__ wt, const float* __restrict__ bt) {
    __shared__ float s_sm[Cn], u_sm[Cn];
    int b = blockIdx.x, c = threadIdx.x;
    s_sm[c] = g_s[b * Cn + c];
    float xk = x_key[b * Cn + c];
    __syncthreads();
    float r = bv[c];
    const float* wr = wv + c * Cn;
    #pragma unroll 8
    for (int c2 = 0; c2 < Cn; c2++) r = fmaf(wr[c2], s_sm[c2], r);
    u_sm[c] = xk - r;
    __syncthreads();
    float tv = bt[c];
    const float* wr2 = wt + c * Cn;
    #pragma unroll 8
    for (int c2 = 0; c2 < Cn; c2++) tv = fmaf(wr2[c2], u_sm[c2], tv);
    g_t[b * Cn + c] = tv;
}

// ---------------- Kernel E2: BN (batch stats) + ReLU + residual --------------
__global__ void kE2(const float* __restrict__ x_key, const float* __restrict__ gamma,
                    const float* __restrict__ beta, float* __restrict__ out) {
    __shared__ float rs[128], rs2[128];
    int c = blockIdx.x, b = threadIdx.x;
    float tv = g_t[b * Cn + c];
    rs[b] = tv; rs2[b] = tv * tv;
    __syncthreads();
    for (int s = 64; s > 0; s >>= 1) {
        if (b < s) { rs[b] += rs[b + s]; rs2[b] += rs2[b + s]; }
        __syncthreads();
    }
    float mean = rs[0] * (1.f / Bn);
    float var  = rs2[0] * (1.f / Bn) - mean * mean;
    float val = (tv - mean) * rsqrtf(var + 1e-5f) * gamma[c] + beta[c];
    out[b * Cn + c] = x_key[b * Cn + c] + fmaxf(val, 0.f);
}

// ---------------- launch ----------------
extern "C" void kernel_launch(void* const* d_in, const int* in_sizes, int n_in,
                              void* d_out, int out_size) {
    const float* x     = (const float*)d_in[0];
    const float* x_key = (const float*)d_in[1];
    const float* wq    = (const float*)d_in[2];
    const float* bq    = (const float*)d_in[3];
    const float* wk    = (const float*)d_in[4];
    const float* bk    = (const float*)d_in[5];
    const float* wv    = (const float*)d_in[6];
    const float* bv    = (const float*)d_in[7];
    const float* wt    = (const float*)d_in[8];
    const float* bt    = (const float*)d_in[9];
    const float* gamma = (const float*)d_in[10];
    const float* beta  = (const float*)d_in[11];

    float* out_final = (float*)d_out;               // (B, C)
    float* out_att   = (float*)d_out + Bn * Cn;     // (B, N)

    cudaFuncSetAttribute(kBm, cudaFuncAttributeMaxDynamicSharedMemorySize, SMEM_TOT);

    kA<<<Bn, 64>>>(x_key, wk, bk);
    kBm<<<Bn * NCH, 256, SMEM_TOT>>>(x, wq, bq);
    kC<<<Bn, 256>>>(out_att);
    kD<<<(Bn * Cn) / 8, 256>>>(x, out_att);
    kE1<<<Bn, Cn>>>(x_key, wv, bv, wt, bt);
    kE2<<<Cn, Bn>>>(x_key, gamma, beta, out_final);
}

// round 14
// speedup vs baseline: 1.9315x; 1.0083x over previous
#include <cuda_runtime.h>
#include <cuda_bf16.h>
#include <cstdint>
#include <math.h>

// Problem constants
#define Bn   128
#define Cn   256
#define Nn   4096
#define CQn  64
#define NBB  128             // n-points per block in kBm
#define NCH  (Nn / NBB)      // 32

// ---------------- scratch ----------------
__device__ float g_tk[Bn * CQn];        // tanh(k)  (B, 64)
__device__ float g_energy[Bn * Nn];     // (B, N)
__device__ float g_s[Bn * Cn];          // weighted sums (B, C)
__device__ float g_t[Bn * Cn];          // pre-BN t (B, C)

// ---------------- helpers ----------------
__device__ __forceinline__ uint32_t smem_u32(const void* p) {
    uint32_t a;
    asm("{ .reg .u64 t; cvta.to.shared.u64 t, %1; cvt.u32.u64 %0, t; }" : "=r"(a) : "l"(p));
    return a;
}
__device__ __forceinline__ void ldsm_x4(uint32_t* r, uint32_t a) {
    asm volatile("ldmatrix.sync.aligned.m8n8.x4.shared.b16 {%0,%1,%2,%3}, [%4];"
                 : "=r"(r[0]), "=r"(r[1]), "=r"(r[2]), "=r"(r[3]) : "r"(a));
}
__device__ __forceinline__ void ldsm_x2t(uint32_t* r, uint32_t a) {
    asm volatile("ldmatrix.sync.aligned.m8n8.x2.trans.shared.b16 {%0,%1}, [%2];"
                 : "=r"(r[0]), "=r"(r[1]) : "r"(a));
}
__device__ __forceinline__ void mma16816(float* c, const uint32_t* a, const uint32_t* b) {
    asm volatile(
        "mma.sync.aligned.m16n8k16.row.col.f32.bf16.bf16.f32 "
        "{%0,%1,%2,%3}, {%4,%5,%6,%7}, {%8,%9}, {%0,%1,%2,%3};"
        : "+f"(c[0]), "+f"(c[1]), "+f"(c[2]), "+f"(c[3])
        : "r"(a[0]), "r"(a[1]), "r"(a[2]), "r"(a[3]), "r"(b[0]), "r"(b[1]));
}
__device__ __forceinline__ void pack4_split(float4 v, uint2& hi, uint2& lo) {
    __nv_bfloat16 h0 = __float2bfloat16(v.x), h1 = __float2bfloat16(v.y);
    __nv_bfloat16 h2 = __float2bfloat16(v.z), h3 = __float2bfloat16(v.w);
    float r0 = v.x - __bfloat162float(h0), r1 = v.y - __bfloat162float(h1);
    float r2 = v.z - __bfloat162float(h2), r3 = v.w - __bfloat162float(h3);
    union { __nv_bfloat16 h[4]; uint2 u; } a, b;
    a.h[0] = h0; a.h[1] = h1; a.h[2] = h2; a.h[3] = h3;
    b.h[0] = __float2bfloat16(r0); b.h[1] = __float2bfloat16(r1);
    b.h[2] = __float2bfloat16(r2); b.h[3] = __float2bfloat16(r3);
    hi = a.u; lo = b.u;
}

// smem layout (bytes), double-buffered tiles
#define WPITCH 72
#define XPITCH 136
#define OFF_WHI 0                      // 64*72*2  = 9216
#define OFF_WLO 9216
#define OFF_XHI 18432                  // 64*136*2 = 17408
#define OFF_XLO 35840
#define BUFSZ   53248
#define OFF_RED (2 * BUFSZ)            // 128*2 f32 = 1024
#define SMEM_TOT (2 * BUFSZ + 1024)

// ---------------- Kernel A: tk[b,o] = tanh(wk . x_key[b] + bk) ----------------
__global__ void kA(const float* __restrict__ x_key, const float* __restrict__ wk,
                   const float* __restrict__ bk) {
    __shared__ float xk[Cn];
    int b = blockIdx.x;
    for (int i = threadIdx.x; i < Cn; i += 64) xk[i] = x_key[b * Cn + i];
    __syncthreads();
    int o = threadIdx.x;
    float acc = bk[o];
    const float* wr = wk + o * Cn;
    #pragma unroll 8
    for (int c = 0; c < Cn; c++) acc = fmaf(wr[c], xk[c], acc);
    g_tk[b * CQn + o] = tanhf(acc);
}

// ---- Kernel B (mma.sync, pipelined): energy[b,n] = sum_o tanh((wq.x)+bq)*tk ----
__global__ __launch_bounds__(256, 2) void kBm(const float* __restrict__ x,
                                              const float* __restrict__ wq,
                                              const float* __restrict__ bq) {
    extern __shared__ char sm[];
    float* red = (float*)(sm + OFF_RED);

    const int tid = threadIdx.x, wid = tid >> 5, lane = tid & 31;
    const int b  = blockIdx.x >> 5;
    const int n0 = (blockIdx.x & 31) * NBB;
    const int mrow = wid & 1, ncol = wid >> 1;
    const int g = lane >> 2, tig = lane & 3;

    float acc[2][4][4];
    #pragma unroll
    for (int mt = 0; mt < 2; mt++)
        #pragma unroll
        for (int nt = 0; nt < 4; nt++)
            #pragma unroll
            for (int j = 0; j < 4; j++) acc[mt][nt][j] = 0.f;

    // per-thread fragment addresses relative to buffer base
    const uint32_t sb = smem_u32(sm);
    const uint32_t a_rel = (uint32_t)(OFF_WHI + ((mrow * 32 + (lane & 15)) * WPITCH + (lane >> 4) * 8) * 2);
    const uint32_t b_rel = (uint32_t)(OFF_XHI + ((lane & 15) * XPITCH + ncol * 32) * 2);
    const uint32_t HL_W = (uint32_t)(OFF_WLO - OFF_WHI);
    const uint32_t HL_X = (uint32_t)(OFF_XLO - OFF_XHI);

    // x-tile prefetch registers: 8 float4 per thread per tile
    float4 xv[8];
    const int xk_row = tid >> 5;               // base row (k) for j-strided loads
    const int xn4 = (tid & 31) * 4;

    // ---- tile load/store lambdas ----
    auto load_x_regs = [&](int ksub) {
        #pragma unroll
        for (int j = 0; j < 8; j++) {
            int k = xk_row + j * 8;
            xv[j] = *(const float4*)(x + ((size_t)(b * Cn + ksub * 64 + k)) * Nn + n0 + xn4);
        }
    };
    auto store_tile = [&](int p, int ksub) {
        char* buf = sm + p * BUFSZ;
        __nv_bfloat16* whi = (__nv_bfloat16*)(buf + OFF_WHI);
        __nv_bfloat16* wlo = (__nv_bfloat16*)(buf + OFF_WLO);
        __nv_bfloat16* xhi = (__nv_bfloat16*)(buf + OFF_XHI);
        __nv_bfloat16* xlo = (__nv_bfloat16*)(buf + OFF_XLO);
        #pragma unroll
        for (int j = 0; j < 8; j++) {
            int k = xk_row + j * 8;
            uint2 h, l; pack4_split(xv[j], h, l);
            *(uint2*)(xhi + k * XPITCH + xn4) = h;
            *(uint2*)(xlo + k * XPITCH + xn4) = l;
        }
        #pragma unroll
        for (int j = 0; j < 4; j++) {
            int i = tid + j * 256;
            int o = i >> 4, k4 = (i & 15) * 4;
            float4 v = *(const float4*)(wq + o * Cn + ksub * 64 + k4);
            uint2 h, l; pack4_split(v, h, l);
            *(uint2*)(whi + o * WPITCH + k4) = h;
            *(uint2*)(wlo + o * WPITCH + k4) = l;
        }
    };
    auto compute = [&](int p) {
        const uint32_t base = sb + (uint32_t)(p * BUFSZ);
        const uint32_t a_base = base + a_rel;
        const uint32_t b_base = base + b_rel;
        #pragma unroll
        for (int kst = 0; kst < 4; kst++) {
            uint32_t ahi[2][4], alo[2][4];
            uint32_t a_addr = a_base + (uint32_t)(kst * 16 * 2);
            ldsm_x4(ahi[0], a_addr);
            ldsm_x4(alo[0], a_addr + HL_W);
            ldsm_x4(ahi[1], a_addr + (uint32_t)(16 * WPITCH * 2));
            ldsm_x4(alo[1], a_addr + (uint32_t)(16 * WPITCH * 2) + HL_W);

            uint32_t b_addr0 = b_base + (uint32_t)(kst * 16 * XPITCH * 2);
            #pragma unroll
            for (int nt = 0; nt < 4; nt++) {
                uint32_t bh[2], bl[2];
                uint32_t baddr = b_addr0 + (uint32_t)(nt * 8 * 2);
                ldsm_x2t(bh, baddr);
                ldsm_x2t(bl, baddr + HL_X);
                #pragma unroll
                for (int mt = 0; mt < 2; mt++) {
                    mma16816(acc[mt][nt], ahi[mt], bh);
                    mma16816(acc[mt][nt], ahi[mt], bl);
                    mma16816(acc[mt][nt], alo[mt], bh);
                }
            }
        }
    };

    // ---- pipelined mainloop ----
    load_x_regs(0);
    store_tile(0, 0);
    __syncthreads();
    #pragma unroll
    for (int ksub = 0; ksub < 4; ksub++) {
        if (ksub < 3) load_x_regs(ksub + 1);   // LDGs overlap with MMAs below
        compute(ksub & 1);
        if (ksub < 3) {
            store_tile((ksub + 1) & 1, ksub + 1);
            __syncthreads();
        }
    }

    // epilogue: tanh(q + bq)*tk, reduce over o (64)
    float p[4][2];
    #pragma unroll
    for (int nt = 0; nt < 4; nt++) { p[nt][0] = 0.f; p[nt][1] = 0.f; }
    #pragma unroll
    for (int mt = 0; mt < 2; mt++) {
        int ob = mrow * 32 + mt * 16 + g;
        float tk0 = g_tk[b * CQn + ob],     bq0 = bq[ob];
        float tk8 = g_tk[b * CQn + ob + 8], bq8 = bq[ob + 8];
        #pragma unroll
        for (int nt = 0; nt < 4; nt++) {
            p[nt][0] += tanhf(acc[mt][nt][0] + bq0) * tk0 + tanhf(acc[mt][nt][2] + bq8) * tk8;
            p[nt][1] += tanhf(acc[mt][nt][1] + bq0) * tk0 + tanhf(acc[mt][nt][3] + bq8) * tk8;
        }
    }
    #pragma unroll
    for (int mask = 4; mask <= 16; mask <<= 1)
        #pragma unroll
        for (int nt = 0; nt < 4; nt++) {
            p[nt][0] += __shfl_xor_sync(0xffffffffu, p[nt][0], mask);
            p[nt][1] += __shfl_xor_sync(0xffffffffu, p[nt][1], mask);
        }
    __syncthreads();   // tiles no longer needed; red region is separate but keep ordering cheap
    if (g == 0) {
        #pragma unroll
        for (int nt = 0; nt < 4; nt++) {
            int n = ncol * 32 + nt * 8 + 2 * tig;
            red[n * 2 + mrow]       = p[nt][0];
            red[(n + 1) * 2 + mrow] = p[nt][1];
        }
    }
    __syncthreads();
    if (tid < NBB)
        g_energy[(size_t)b * Nn + n0 + tid] = red[tid * 2] + red[tid * 2 + 1];
}

// ---------------- Kernel C: softmax over N per batch -> att (into d_out) ------
__global__ void kC(float* __restrict__ att_out) {
    __shared__ float red[256];
    int b = blockIdx.x, tid = threadIdx.x;
    const float* e = g_energy + (size_t)b * Nn;
    float m = -1e30f;
    for (int i = tid; i < Nn; i += 256) m = fmaxf(m, e[i]);
    red[tid] = m; __syncthreads();
    for (int s = 128; s > 0; s >>= 1) {
        if (tid < s) red[tid] = fmaxf(red[tid], red[tid + s]);
        __syncthreads();
    }
    m = red[0]; __syncthreads();
    float z = 0.f;
    for (int i = tid; i < Nn; i += 256) z += expf(e[i] - m);
    red[tid] = z; __syncthreads();
    for (int s = 128; s > 0; s >>= 1) {
        if (tid < s) red[tid] += red[tid + s];
        __syncthreads();
    }
    float inv = 1.f / red[0];
    float* out = att_out + (size_t)b * Nn;
    for (int i = tid; i < Nn; i += 256) out[i] = expf(e[i] - m) * inv;
}

// ---------------- Kernel D: s[b,c] = dot(x[b,c,:], att[b,:]) ----------------
__global__ void kD(const float* __restrict__ x, const float* __restrict__ att) {
    int row = blockIdx.x * 8 + (threadIdx.x >> 5);   // row = b*C + c
    int lane = threadIdx.x & 31;
    int b = row >> 8;
    const float4* xr = (const float4*)(x + (size_t)row * Nn);
    const float4* ar = (const float4*)(att + (size_t)b * Nn);
    float acc = 0.f;
    #pragma unroll 4
    for (int i = lane; i < Nn / 4; i += 32) {
        float4 xv = xr[i], av = ar[i];
        acc += xv.x * av.x + xv.y * av.y + xv.z * av.z + xv.w * av.w;
    }
    #pragma unroll
    for (int o = 16; o > 0; o >>= 1) acc += __shfl_down_sync(0xffffffffu, acc, o);
    if (lane == 0) g_s[row] = acc;
}

// ---------------- Kernel E1: r = wv.s + bv ; t = wt.(x_key - r) + bt ----------
__global__ void kE1(const float* __restrict__ x_key,
                    const float* __restrict__ wv, const float* __restrict__ bv,
                    const float* __restrict__ wt, const float* __restrict__ bt) {
    __shared__ float s_sm[Cn], u_sm[Cn];
    int b = blockIdx.x, c = threadIdx.x;
    s_sm[c] = g_s[b * Cn + c];
    float xk = x_key[b * Cn + c];
    __syncthreads();
    float r = bv[c];
    const float* wr = wv + c * Cn;
    #pragma unroll 8
    for (int c2 = 0; c2 < Cn; c2++) r = fmaf(wr[c2], s_sm[c2], r);
    u_sm[c] = xk - r;
    __syncthreads();
    float tv = bt[c];
    const float* wr2 = wt + c * Cn;
    #pragma unroll 8
    for (int c2 = 0; c2 < Cn; c2++) tv = fmaf(wr2[c2], u_sm[c2], tv);
    g_t[b * Cn + c] = tv;
}

// ---------------- Kernel E2: BN (batch stats) + ReLU + residual --------------
__global__ void kE2(const float* __restrict__ x_key, const float* __restrict__ gamma,
                    const float* __restrict__ beta, float* __restrict__ out) {
    __shared__ float rs[128], rs2[128];
    int c = blockIdx.x, b = threadIdx.x;
    float tv = g_t[b * Cn + c];
    rs[b] = tv; rs2[b] = tv * tv;
    __syncthreads();
    for (int s = 64; s > 0; s >>= 1) {
        if (b < s) { rs[b] += rs[b + s]; rs2[b] += rs2[b + s]; }
        __syncthreads();
    }
    float mean = rs[0] * (1.f / Bn);
    float var  = rs2[0] * (1.f / Bn) - mean * mean;
    float val = (tv - mean) * rsqrtf(var + 1e-5f) * gamma[c] + beta[c];
    out[b * Cn + c] = x_key[b * Cn + c] + fmaxf(val, 0.f);
}

// ---------------- launch ----------------
extern "C" void kernel_launch(void* const* d_in, const int* in_sizes, int n_in,
                              void* d_out, int out_size) {
    const float* x     = (const float*)d_in[0];
    const float* x_key = (const float*)d_in[1];
    const float* wq    = (const float*)d_in[2];
    const float* bq    = (const float*)d_in[3];
    const float* wk    = (const float*)d_in[4];
    const float* bk    = (const float*)d_in[5];
    const float* wv    = (const float*)d_in[6];
    const float* bv    = (const float*)d_in[7];
    const float* wt    = (const float*)d_in[8];
    const float* bt    = (const float*)d_in[9];
    const float* gamma = (const float*)d_in[10];
    const float* beta  = (const float*)d_in[11];

    float* out_final = (float*)d_out;               // (B, C)
    float* out_att   = (float*)d_out + Bn * Cn;     // (B, N)

    cudaFuncSetAttribute(kBm, cudaFuncAttributeMaxDynamicSharedMemorySize, SMEM_TOT);

    kA<<<Bn, 64>>>(x_key, wk, bk);
    kBm<<<Bn * NCH, 256, SMEM_TOT>>>(x, wq, bq);
    kC<<<Bn, 256>>>(out_att);
    kD<<<(Bn * Cn) / 8, 256>>>(x, out_att);
    kE1<<<Bn, Cn>>>(x_key, wv, bv, wt, bt);
    kE2<<<Cn, Bn>>>(x_key, gamma, beta, out_final);
}